// round 16
// baseline (speedup 1.0000x reference)
#include <cuda_runtime.h>
#include <cuda_fp16.h>
#include <math.h>
#include <stdint.h>

// ---------------- problem constants ----------------
#define BB   2
#define TT   2048
#define CC   1024
#define HH   16
#define DD   64
#define FF   4096
#define MM   (BB*TT)          // 4096 rows
#define QKVC (3*CC)           // 3072

// ---------------- scratch (device globals; no allocs allowed) ----------------
__device__ float g_x1 [MM*CC];                   // residual stream after attn
__device__ alignas(128) __half g_h [MM*CC];      // LN out fp16
__device__ alignas(128) __half g_q [MM*QKVC];    // qkv fp16 (Q pre-scaled by 1/8)
__device__ alignas(128) __half g_a [MM*CC];      // attn out fp16
__device__ alignas(128) __half g_f [MM*FF];      // gelu out fp16
// fp16 weights, SAME layout as input: W[K][N]
__device__ alignas(128) __half g_wqkv[CC*QKVC];
__device__ alignas(128) __half g_wout[CC*CC];
__device__ alignas(128) __half g_wff1[CC*FF];
__device__ alignas(128) __half g_wff2[FF*CC];

// ================= helpers =================
__device__ __forceinline__ uint32_t smem_to_u32(const void* p) {
    uint32_t a;
    asm("{ .reg .u64 t; cvta.to.shared.u64 t, %1; cvt.u32.u64 %0, t; }" : "=r"(a) : "l"(p));
    return a;
}
#define CP_ASYNC16(dst, src) \
    asm volatile("cp.async.cg.shared.global [%0], [%1], 16;" :: "r"(dst), "l"(src))
#define CP_COMMIT() asm volatile("cp.async.commit_group;" ::: "memory")
#define CP_WAIT(n)  asm volatile("cp.async.wait_group %0;" :: "n"(n) : "memory")

__device__ __forceinline__ void ldsm4(uint32_t* r, uint32_t addr) {
    asm volatile("ldmatrix.sync.aligned.m8n8.x4.shared.b16 {%0,%1,%2,%3}, [%4];"
                 : "=r"(r[0]), "=r"(r[1]), "=r"(r[2]), "=r"(r[3]) : "r"(addr));
}
__device__ __forceinline__ void ldsm4t(uint32_t* r, uint32_t addr) {
    asm volatile("ldmatrix.sync.aligned.m8n8.x4.trans.shared.b16 {%0,%1,%2,%3}, [%4];"
                 : "=r"(r[0]), "=r"(r[1]), "=r"(r[2]), "=r"(r[3]) : "r"(addr));
}
__device__ __forceinline__ void mma16816(float* c, const uint32_t* a, const uint32_t* b) {
    asm volatile("mma.sync.aligned.m16n8k16.row.col.f32.f16.f16.f32 "
                 "{%0,%1,%2,%3}, {%4,%5,%6,%7}, {%8,%9}, {%0,%1,%2,%3};"
                 : "+f"(c[0]), "+f"(c[1]), "+f"(c[2]), "+f"(c[3])
                 : "r"(a[0]), "r"(a[1]), "r"(a[2]), "r"(a[3]), "r"(b[0]), "r"(b[1]));
}
__device__ __forceinline__ uint32_t pack2(float x0, float x1) {
    __half2 h = __floats2half2_rn(x0, x1);
    return *(uint32_t*)&h;
}

// ================= weight convert fp32 -> fp16 (same layout) =================
__global__ void __launch_bounds__(256) wconv_kernel(const float* __restrict__ W,
                                                    __half* __restrict__ Wh)
{
    size_t i = ((size_t)blockIdx.x * 256 + threadIdx.x) * 8;
    float4 a = *(const float4*)(W + i);
    float4 c = *(const float4*)(W + i + 4);
    uint4 o;
    o.x = pack2(a.x, a.y); o.y = pack2(a.z, a.w);
    o.z = pack2(c.x, c.y); o.w = pack2(c.z, c.w);
    *(uint4*)(Wh + i) = o;
}

// ================= LayerNorm -> fp16 (vectorized) =================
__global__ void __launch_bounds__(256) ln_kernel(const float* __restrict__ x,
                                                 const float* __restrict__ g,
                                                 const float* __restrict__ b,
                                                 __half* __restrict__ y)
{
    int row = blockIdx.x;
    int tid = threadIdx.x;
    float4 v = ((const float4*)(x + (size_t)row * CC))[tid];
    float s1 = v.x + v.y + v.z + v.w;
    float s2 = v.x * v.x + v.y * v.y + v.z * v.z + v.w * v.w;
#pragma unroll
    for (int o = 16; o; o >>= 1) {
        s1 += __shfl_xor_sync(0xffffffffu, s1, o);
        s2 += __shfl_xor_sync(0xffffffffu, s2, o);
    }
    __shared__ float r1[8], r2[8], sh_mean, sh_rstd;
    if ((tid & 31) == 0) { r1[tid >> 5] = s1; r2[tid >> 5] = s2; }
    __syncthreads();
    if (tid == 0) {
        float t1 = 0.f, t2 = 0.f;
#pragma unroll
        for (int i = 0; i < 8; i++) { t1 += r1[i]; t2 += r2[i]; }
        float mean = t1 * (1.0f / CC);
        float var  = t2 * (1.0f / CC) - mean * mean;
        sh_mean = mean;
        sh_rstd = rsqrtf(var + 1e-5f);
    }
    __syncthreads();
    float mean = sh_mean, rstd = sh_rstd;
    float4 gv = ((const float4*)g)[tid];
    float4 bv = ((const float4*)b)[tid];
    uint2 hv;
    hv.x = pack2((v.x - mean) * rstd * gv.x + bv.x, (v.y - mean) * rstd * gv.y + bv.y);
    hv.y = pack2((v.z - mean) * rstd * gv.z + bv.z, (v.w - mean) * rstd * gv.w + bv.w);
    *(uint2*)(y + (size_t)row * CC + tid * 4) = hv;
}

// ================= mma.sync GEMM (plain fp16, B K-major) =================
// C = A*B + bias   A[M][K] fp16, B = W[K][gN] fp16 (K-major; trans-ldsm frags)
// E: 1 = fp32 out (+bias+res); 2 = gelu -> fp16; 4 = fp16 (+bias; Q cols x1/8).
#define GS 4
#define SSTRIDE 40                          // A smem row stride (halves)
#define TILE_A (128*SSTRIDE*2)              // 10240 bytes
#define SBST 136                            // B smem row stride (halves) = 272B
#define TILE_BK (32*SBST*2)                 // 8704 bytes
#define STAGE_SZ (TILE_A + TILE_BK)         // 18944
#define GSMEM2 (GS * STAGE_SZ)              // 75776

template<int E>
__global__ void __launch_bounds__(256, 2) gemm_mma(const __half* __restrict__ A,
                                                   const __half* __restrict__ B,
                                                   const float* __restrict__ bias,
                                                   const float* __restrict__ res,
                                                   float* __restrict__ outf,
                                                   __half* __restrict__ outh,
                                                   int K, int gN)
{
    extern __shared__ char smem[];
    uint32_t sbase = smem_to_u32(smem);
    int tid = threadIdx.x, lane = tid & 31, wid = tid >> 5;
    int bx = blockIdx.x, by = blockIdx.y;
    const int NK = K >> 5;
    int m0 = (wid & 3) * 32, n0 = (wid >> 2) * 64;

    const __half* Ap = A + (size_t)(by * 128) * K;
    const __half* Bp = B + bx * 128;         // [K][gN], col offset

    int uA = tid & 3;        // A: 16B unit within 64B row
    int rA = tid >> 2;       // 0..63
    int uB = tid & 15;       // B: 16B unit within 256B row
    int rB = tid >> 4;       // 0..15

    auto issue = [&](int kk) {
        uint32_t st = sbase + (kk & (GS - 1)) * STAGE_SZ;
#pragma unroll
        for (int rr = 0; rr < 2; rr++) {
            int r = rA + rr * 64;
            CP_ASYNC16(st + (r * SSTRIDE + uA * 8) * 2,
                       Ap + (size_t)r * K + kk * 32 + uA * 8);
        }
        uint32_t stB = st + TILE_A;
#pragma unroll
        for (int rr = 0; rr < 2; rr++) {
            int r = rB + rr * 16;
            CP_ASYNC16(stB + (r * SBST + uB * 8) * 2,
                       Bp + (size_t)(kk * 32 + r) * gN + uB * 8);
        }
        CP_COMMIT();
    };

    float acc[2][8][4] = {};

    for (int c = 0; c < GS - 1; c++) issue(c);

    for (int c = 0; c < NK; c++) {
        CP_WAIT(GS - 2);          // stage c complete
        __syncthreads();          // all warps done reading stage (c-1)
        if (c + GS - 1 < NK) issue(c + GS - 1); else CP_COMMIT();

        uint32_t st = sbase + (c & (GS - 1)) * STAGE_SZ;
        uint32_t stB = st + TILE_A;
#pragma unroll
        for (int kh = 0; kh < 2; kh++) {
            uint32_t ah[2][4];
#pragma unroll
            for (int i = 0; i < 2; i++) {
                uint32_t aoff = ((m0 + i * 16 + (lane & 15)) * SSTRIDE + kh * 16 + (lane >> 4) * 8) * 2;
                ldsm4(ah[i], st + aoff);
            }
            // B frags: trans-ldsm over [k][n] tile
            uint32_t boff = (kh * 16 + (lane & 15)) * SBST + n0 + ((lane >> 4) & 1) * 8;
            uint32_t bh[4][4];
#pragma unroll
            for (int g = 0; g < 4; g++) ldsm4t(bh[g], stB + (boff + g * 16) * 2);
#pragma unroll
            for (int i = 0; i < 2; i++)
#pragma unroll
                for (int g = 0; g < 4; g++) {
                    mma16816(acc[i][g * 2 + 0], ah[i], &bh[g][0]);
                    mma16816(acc[i][g * 2 + 1], ah[i], &bh[g][2]);
                }
        }
    }

    // epilogue from registers
    int mb = by * 128 + m0;
    int nb = bx * 128 + n0;
#pragma unroll
    for (int i = 0; i < 2; i++) {
#pragma unroll
        for (int j = 0; j < 8; j++) {
            float* cc = acc[i][j];
            int n = nb + j * 8 + (lane & 3) * 2;
            float b0 = bias[n], b1 = bias[n + 1];
#pragma unroll
            for (int hrow = 0; hrow < 2; hrow++) {
                int m = mb + i * 16 + (lane >> 2) + hrow * 8;
                float v0 = cc[hrow * 2 + 0] + b0;
                float v1 = cc[hrow * 2 + 1] + b1;
                size_t off = (size_t)m * gN + n;
                if (E == 1) {
                    float2 rv = *(const float2*)(res + off);
                    v0 += rv.x; v1 += rv.y;
                    float2 ov; ov.x = v0; ov.y = v1;
                    *(float2*)(outf + off) = ov;
                } else if (E == 4) {
                    // Q columns pre-scaled by 1/sqrt(D)=0.125 (exact pow2)
                    if (n < CC) { v0 *= 0.125f; v1 *= 0.125f; }
                    *(uint32_t*)(outh + off) = pack2(v0, v1);
                } else {
                    v0 = 0.5f * v0 * (1.0f + erff(v0 * 0.70710678118654752f));
                    v1 = 0.5f * v1 * (1.0f + erff(v1 * 0.70710678118654752f));
                    *(uint32_t*)(outh + off) = pack2(v0, v1);
                }
            }
        }
    }
}

// ================= FA2 tensor-core attention (fp16, cp.async) =====
// Q pre-scaled by 1/8 in qkv epilogue. Called per-batch (pointers pre-offset).
#define AST 72        // smem row stride in halves
#define ATILE (64 * AST)                 // halves per tile
#define KVSTAGE (2 * ATILE)              // K,V
#define ASMEM ((ATILE + 2 * KVSTAGE) * 2)   // 46080 bytes

__global__ void __launch_bounds__(128) attn_fa2(const __half* __restrict__ q_g,
                                                __half* __restrict__ o_g)
{
    extern __shared__ __half sb[];
    __half* sQ = sb;
    __half* sKV = sQ + ATILE;    // 2 stages of [K|V]
    uint32_t uQ = smem_to_u32(sQ);
    uint32_t uKV = smem_to_u32(sKV);

    int tid = threadIdx.x, lane = tid & 31, w = tid >> 5;
    int qt = gridDim.x - 1 - blockIdx.x;       // heavy tiles first
    int h = blockIdx.y;
    size_t qbase = ((size_t)(qt * 64)) * QKVC + h * DD;

    int r0 = tid >> 3, uu = tid & 7;

    auto issue_kv = [&](int kt, int s) {
        size_t kbase = ((size_t)(kt * 64)) * QKVC + CC + h * DD;
        size_t vbase = kbase + CC;
        uint32_t st = uKV + s * KVSTAGE * 2;
#pragma unroll
        for (int rep = 0; rep < 4; rep++) {
            int r = r0 + rep * 16;
            size_t go = (size_t)r * QKVC + uu * 8;
            uint32_t so = (r * AST + uu * 8) * 2;
            CP_ASYNC16(st + so,             q_g + kbase + go);
            CP_ASYNC16(st + ATILE * 2 + so, q_g + vbase + go);
        }
        CP_COMMIT();
    };

    issue_kv(0, 0);
#pragma unroll
    for (int rep = 0; rep < 4; rep++) {
        int r = r0 + rep * 16;
        *(uint4*)(sQ + r * AST + uu * 8) = *(const uint4*)(q_g + qbase + (size_t)r * QKVC + uu * 8);
    }
    __syncthreads();

    uint32_t qh[4][4];
#pragma unroll
    for (int ks = 0; ks < 4; ks++) {
        uint32_t off = ((16 * w + (lane & 15)) * AST + ks * 16 + (lane >> 4) * 8) * 2;
        ldsm4(qh[ks], uQ + off);
    }

    float m0r = -1e30f, m1r = -1e30f;
    float l0r = 0.f, l1r = 0.f;
    float oacc[8][4] = {};

    for (int kt = 0; kt <= qt; kt++) {
        int s = kt & 1;
        __syncthreads();
        if (kt + 1 <= qt) issue_kv(kt + 1, s ^ 1); else CP_COMMIT();
        CP_WAIT(1);
        __syncthreads();

        uint32_t uK = uKV + (s * KVSTAGE) * 2;
        uint32_t uV = uK + ATILE * 2;

        // ---- S = QK^T (Q pre-scaled) ----
        float sacc[8][4] = {};
#pragma unroll
        for (int ks = 0; ks < 4; ks++) {
            uint32_t kb[4][4];
            uint32_t boff = ((lane & 7) + ((lane >> 4) & 1) * 8) * AST + ks * 16 + ((lane >> 3) & 1) * 8;
#pragma unroll
            for (int g = 0; g < 4; g++) ldsm4(kb[g], uK + (boff + g * 16 * AST) * 2);
#pragma unroll
            for (int g = 0; g < 4; g++) {
                mma16816(sacc[g * 2 + 0], qh[ks], &kb[g][0]);
                mma16816(sacc[g * 2 + 1], qh[ks], &kb[g][2]);
            }
        }

        // ---- mask, online softmax ----
        int rl0 = w * 16 + (lane >> 2);
        int rl1 = rl0 + 8;
        float mn0 = m0r, mn1 = m1r;
#pragma unroll
        for (int t = 0; t < 8; t++) {
            if (kt == qt) {
                int col = t * 8 + 2 * (lane & 3);
                if (col     > rl0) sacc[t][0] = -1e30f;
                if (col + 1 > rl0) sacc[t][1] = -1e30f;
                if (col     > rl1) sacc[t][2] = -1e30f;
                if (col + 1 > rl1) sacc[t][3] = -1e30f;
            }
            mn0 = fmaxf(mn0, fmaxf(sacc[t][0], sacc[t][1]));
            mn1 = fmaxf(mn1, fmaxf(sacc[t][2], sacc[t][3]));
        }
        mn0 = fmaxf(mn0, __shfl_xor_sync(0xffffffffu, mn0, 1));
        mn0 = fmaxf(mn0, __shfl_xor_sync(0xffffffffu, mn0, 2));
        mn1 = fmaxf(mn1, __shfl_xor_sync(0xffffffffu, mn1, 1));
        mn1 = fmaxf(mn1, __shfl_xor_sync(0xffffffffu, mn1, 2));
        float es0 = __expf(m0r - mn0), es1 = __expf(m1r - mn1);
        m0r = mn0; m1r = mn1;
        float rs0 = 0.f, rs1 = 0.f;
#pragma unroll
        for (int t = 0; t < 8; t++) {
            sacc[t][0] = __expf(sacc[t][0] - mn0);
            sacc[t][1] = __expf(sacc[t][1] - mn0);
            sacc[t][2] = __expf(sacc[t][2] - mn1);
            sacc[t][3] = __expf(sacc[t][3] - mn1);
            rs0 += sacc[t][0] + sacc[t][1];
            rs1 += sacc[t][2] + sacc[t][3];
        }
        rs0 += __shfl_xor_sync(0xffffffffu, rs0, 1);
        rs0 += __shfl_xor_sync(0xffffffffu, rs0, 2);
        rs1 += __shfl_xor_sync(0xffffffffu, rs1, 1);
        rs1 += __shfl_xor_sync(0xffffffffu, rs1, 2);
        l0r = l0r * es0 + rs0;
        l1r = l1r * es1 + rs1;
#pragma unroll
        for (int t = 0; t < 8; t++) {
            oacc[t][0] *= es0; oacc[t][1] *= es0;
            oacc[t][2] *= es1; oacc[t][3] *= es1;
        }

        // ---- PV ----
#pragma unroll
        for (int ks = 0; ks < 4; ks++) {
            uint32_t pa[4];
            pa[0] = pack2(sacc[2 * ks][0],     sacc[2 * ks][1]);
            pa[1] = pack2(sacc[2 * ks][2],     sacc[2 * ks][3]);
            pa[2] = pack2(sacc[2 * ks + 1][0], sacc[2 * ks + 1][1]);
            pa[3] = pack2(sacc[2 * ks + 1][2], sacc[2 * ks + 1][3]);

            uint32_t vb[4][4];
            uint32_t voff = (ks * 16 + (lane & 15)) * AST + ((lane >> 4) & 1) * 8;
#pragma unroll
            for (int g = 0; g < 4; g++) ldsm4t(vb[g], uV + (voff + g * 16) * 2);
#pragma unroll
            for (int g = 0; g < 4; g++) {
                mma16816(oacc[g * 2 + 0], pa, &vb[g][0]);
                mma16816(oacc[g * 2 + 1], pa, &vb[g][2]);
            }
        }
    }

    float inv0 = 1.0f / l0r, inv1 = 1.0f / l1r;
    size_t r0g = (size_t)(qt * 64 + w * 16 + (lane >> 2));
    size_t obase0 = r0g * CC + h * DD;
    size_t obase1 = (r0g + 8) * CC + h * DD;
#pragma unroll
    for (int t = 0; t < 8; t++) {
        int d = t * 8 + 2 * (lane & 3);
        *(uint32_t*)(o_g + obase0 + d) = pack2(oacc[t][0] * inv0, oacc[t][1] * inv0);
        *(uint32_t*)(o_g + obase1 + d) = pack2(oacc[t][2] * inv1, oacc[t][3] * inv1);
    }
}

// ---------------- launch: two per-batch chains, phase-staggered ----------------
extern "C" void kernel_launch(void* const* d_in, const int* in_sizes, int n_in,
                              void* d_out, int out_size)
{
    const float* x     = (const float*)d_in[0];
    const float* ln1_g = (const float*)d_in[1];
    const float* ln1_b = (const float*)d_in[2];
    const float* qkv_w = (const float*)d_in[3];
    const float* qkv_b = (const float*)d_in[4];
    const float* out_w = (const float*)d_in[5];
    const float* out_b = (const float*)d_in[6];
    const float* ln2_g = (const float*)d_in[7];
    const float* ln2_b = (const float*)d_in[8];
    const float* ff1_w = (const float*)d_in[9];
    const float* ff1_b = (const float*)d_in[10];
    const float* ff2_w = (const float*)d_in[11];
    const float* ff2_b = (const float*)d_in[12];
    float* y = (float*)d_out;

    float *p_x1;
    __half *p_h, *p_q, *p_a, *p_f;
    __half *p_wq, *p_wo, *p_w1, *p_w2;
    cudaGetSymbolAddress((void**)&p_x1, g_x1);
    cudaGetSymbolAddress((void**)&p_h,  g_h);
    cudaGetSymbolAddress((void**)&p_q,  g_q);
    cudaGetSymbolAddress((void**)&p_a,  g_a);
    cudaGetSymbolAddress((void**)&p_f,  g_f);
    cudaGetSymbolAddress((void**)&p_wq, g_wqkv);
    cudaGetSymbolAddress((void**)&p_wo, g_wout);
    cudaGetSymbolAddress((void**)&p_w1, g_wff1);
    cudaGetSymbolAddress((void**)&p_w2, g_wff2);

    cudaFuncSetAttribute(attn_fa2, cudaFuncAttributeMaxDynamicSharedMemorySize, ASMEM);
    cudaFuncSetAttribute((const void*)gemm_mma<1>, cudaFuncAttributeMaxDynamicSharedMemorySize, GSMEM2);
    cudaFuncSetAttribute((const void*)gemm_mma<2>, cudaFuncAttributeMaxDynamicSharedMemorySize, GSMEM2);
    cudaFuncSetAttribute((const void*)gemm_mma<4>, cudaFuncAttributeMaxDynamicSharedMemorySize, GSMEM2);

    // streams + events, created once OUTSIDE graph capture
    static cudaStream_t s1 = nullptr, s2 = nullptr;
    static cudaEvent_t e0 = nullptr, e_wq = nullptr, e_wmid = nullptr, eB = nullptr, e_qA = nullptr;
    if (!s1) {
        cudaStreamCreateWithFlags(&s1, cudaStreamNonBlocking);
        cudaStreamCreateWithFlags(&s2, cudaStreamNonBlocking);
        cudaEventCreateWithFlags(&e0,    cudaEventDisableTiming);
        cudaEventCreateWithFlags(&e_wq,  cudaEventDisableTiming);
        cudaEventCreateWithFlags(&e_wmid,cudaEventDisableTiming);
        cudaEventCreateWithFlags(&eB,    cudaEventDisableTiming);
        cudaEventCreateWithFlags(&e_qA,  cudaEventDisableTiming);
    }

    // ---- weight converts on s2 ----
    cudaEventRecord(e0, 0);
    cudaStreamWaitEvent(s2, e0, 0);
    wconv_kernel<<<CC * QKVC / 2048, 256, 0, s2>>>(qkv_w, p_wq);
    cudaEventRecord(e_wq, s2);
    wconv_kernel<<<CC * CC / 2048, 256, 0, s2>>>(out_w, p_wo);
    wconv_kernel<<<CC * FF / 2048, 256, 0, s2>>>(ff1_w, p_w1);
    wconv_kernel<<<FF * CC / 2048, 256, 0, s2>>>(ff2_w, p_w2);
    cudaEventRecord(e_wmid, s2);

    // per-batch half sizes (rows = TT)
    const size_t oC  = (size_t)TT * CC;     // half offset, C-wide arrays
    const size_t oQ  = (size_t)TT * QKVC;
    const size_t oF  = (size_t)TT * FF;
    dim3 gQKV(QKVC / 128, TT / 128);
    dim3 gOUT(CC / 128,  TT / 128);
    dim3 gFF1(FF / 128,  TT / 128);
    dim3 gFF2(CC / 128,  TT / 128);
    dim3 gATT(TT / 64, HH, 1);

    // ======== chain A (batch 0) on main stream ========
    ln_kernel<<<TT, 256>>>(x, ln1_g, ln1_b, p_h);
    cudaStreamWaitEvent(0, e_wq, 0);
    gemm_mma<4><<<gQKV, 256, GSMEM2>>>(p_h, p_wq, qkv_b, nullptr, nullptr, p_q, CC, QKVC);
    cudaEventRecord(e_qA, 0);      // phase-stagger anchor
    attn_fa2<<<gATT, 128, ASMEM>>>(p_q, p_a);
    cudaStreamWaitEvent(0, e_wmid, 0);
    gemm_mma<1><<<gOUT, 256, GSMEM2>>>(p_a, p_wo, out_b, x, p_x1, nullptr, CC, CC);
    ln_kernel<<<TT, 256>>>(p_x1, ln2_g, ln2_b, p_h);
    gemm_mma<2><<<gFF1, 256, GSMEM2>>>(p_h, p_w1, ff1_b, nullptr, nullptr, p_f, CC, FF);
    gemm_mma<1><<<gFF2, 256, GSMEM2>>>(p_f, p_w2, ff2_b, p_x1, y, nullptr, FF, CC);

    // ======== chain B (batch 1) on s1, staggered one GEMM behind A ========
    cudaStreamWaitEvent(s1, e0, 0);
    ln_kernel<<<TT, 256, 0, s1>>>(x + oC, ln1_g, ln1_b, p_h + oC);
    cudaStreamWaitEvent(s1, e_wq, 0);
    cudaStreamWaitEvent(s1, e_qA, 0);   // B's qkv starts after A's qkv -> B GEMM overlaps A attn
    gemm_mma<4><<<gQKV, 256, GSMEM2, s1>>>(p_h + oC, p_wq, qkv_b, nullptr, nullptr, p_q + oQ, CC, QKVC);
    attn_fa2<<<gATT, 128, ASMEM, s1>>>(p_q + oQ, p_a + oC);
    cudaStreamWaitEvent(s1, e_wmid, 0);
    gemm_mma<1><<<gOUT, 256, GSMEM2, s1>>>(p_a + oC, p_wo, out_b, x + oC, p_x1 + oC, nullptr, CC, CC);
    ln_kernel<<<TT, 256, 0, s1>>>(p_x1 + oC, ln2_g, ln2_b, p_h + oC);
    gemm_mma<2><<<gFF1, 256, GSMEM2, s1>>>(p_h + oC, p_w1, ff1_b, nullptr, nullptr, p_f + oF, CC, FF);
    gemm_mma<1><<<gFF2, 256, GSMEM2, s1>>>(p_f + oF, p_w2, ff2_b, p_x1 + oC, y + oC, nullptr, FF, CC);
    cudaEventRecord(eB, s1);

    // join
    cudaStreamWaitEvent(0, eB, 0);
}

// round 17
// speedup vs baseline: 1.0358x; 1.0358x over previous
#include <cuda_runtime.h>
#include <cuda_fp16.h>
#include <math.h>
#include <stdint.h>

// ---------------- problem constants ----------------
#define BB   2
#define TT   2048
#define CC   1024
#define HH   16
#define DD   64
#define FF   4096
#define MM   (BB*TT)          // 4096 rows
#define QKVC (3*CC)           // 3072

// ---------------- scratch (device globals; no allocs allowed) ----------------
__device__ float g_x1 [MM*CC];                   // residual stream after attn
__device__ alignas(128) __half g_h [MM*CC];      // LN out fp16
__device__ alignas(128) __half g_q [MM*QKVC];    // qkv fp16 (Q pre-scaled by 1/8)
__device__ alignas(128) __half g_a [MM*CC];      // attn out fp16
__device__ alignas(128) __half g_f [MM*FF];      // gelu out fp16
// fp16 weights, SAME layout as input: W[K][N]
__device__ alignas(128) __half g_wqkv[CC*QKVC];
__device__ alignas(128) __half g_wout[CC*CC];
__device__ alignas(128) __half g_wff1[CC*FF];
__device__ alignas(128) __half g_wff2[FF*CC];

// ================= helpers =================
__device__ __forceinline__ uint32_t smem_to_u32(const void* p) {
    uint32_t a;
    asm("{ .reg .u64 t; cvta.to.shared.u64 t, %1; cvt.u32.u64 %0, t; }" : "=r"(a) : "l"(p));
    return a;
}
#define CP_ASYNC16(dst, src) \
    asm volatile("cp.async.cg.shared.global [%0], [%1], 16;" :: "r"(dst), "l"(src))
#define CP_COMMIT() asm volatile("cp.async.commit_group;" ::: "memory")
#define CP_WAIT(n)  asm volatile("cp.async.wait_group %0;" :: "n"(n) : "memory")

__device__ __forceinline__ void ldsm4(uint32_t* r, uint32_t addr) {
    asm volatile("ldmatrix.sync.aligned.m8n8.x4.shared.b16 {%0,%1,%2,%3}, [%4];"
                 : "=r"(r[0]), "=r"(r[1]), "=r"(r[2]), "=r"(r[3]) : "r"(addr));
}
__device__ __forceinline__ void ldsm4t(uint32_t* r, uint32_t addr) {
    asm volatile("ldmatrix.sync.aligned.m8n8.x4.trans.shared.b16 {%0,%1,%2,%3}, [%4];"
                 : "=r"(r[0]), "=r"(r[1]), "=r"(r[2]), "=r"(r[3]) : "r"(addr));
}
__device__ __forceinline__ void mma16816(float* c, const uint32_t* a, const uint32_t* b) {
    asm volatile("mma.sync.aligned.m16n8k16.row.col.f32.f16.f16.f32 "
                 "{%0,%1,%2,%3}, {%4,%5,%6,%7}, {%8,%9}, {%0,%1,%2,%3};"
                 : "+f"(c[0]), "+f"(c[1]), "+f"(c[2]), "+f"(c[3])
                 : "r"(a[0]), "r"(a[1]), "r"(a[2]), "r"(a[3]), "r"(b[0]), "r"(b[1]));
}
__device__ __forceinline__ uint32_t pack2(float x0, float x1) {
    __half2 h = __floats2half2_rn(x0, x1);
    return *(uint32_t*)&h;
}

// ================= weight convert fp32 -> fp16 (same layout) =================
__global__ void __launch_bounds__(256) wconv_kernel(const float* __restrict__ W,
                                                    __half* __restrict__ Wh)
{
    size_t i = ((size_t)blockIdx.x * 256 + threadIdx.x) * 8;
    float4 a = *(const float4*)(W + i);
    float4 c = *(const float4*)(W + i + 4);
    uint4 o;
    o.x = pack2(a.x, a.y); o.y = pack2(a.z, a.w);
    o.z = pack2(c.x, c.y); o.w = pack2(c.z, c.w);
    *(uint4*)(Wh + i) = o;
}

// ================= LayerNorm -> fp16 (vectorized) =================
__global__ void __launch_bounds__(256) ln_kernel(const float* __restrict__ x,
                                                 const float* __restrict__ g,
                                                 const float* __restrict__ b,
                                                 __half* __restrict__ y)
{
    int row = blockIdx.x;
    int tid = threadIdx.x;
    float4 v = ((const float4*)(x + (size_t)row * CC))[tid];
    float s1 = v.x + v.y + v.z + v.w;
    float s2 = v.x * v.x + v.y * v.y + v.z * v.z + v.w * v.w;
#pragma unroll
    for (int o = 16; o; o >>= 1) {
        s1 += __shfl_xor_sync(0xffffffffu, s1, o);
        s2 += __shfl_xor_sync(0xffffffffu, s2, o);
    }
    __shared__ float r1[8], r2[8], sh_mean, sh_rstd;
    if ((tid & 31) == 0) { r1[tid >> 5] = s1; r2[tid >> 5] = s2; }
    __syncthreads();
    if (tid == 0) {
        float t1 = 0.f, t2 = 0.f;
#pragma unroll
        for (int i = 0; i < 8; i++) { t1 += r1[i]; t2 += r2[i]; }
        float mean = t1 * (1.0f / CC);
        float var  = t2 * (1.0f / CC) - mean * mean;
        sh_mean = mean;
        sh_rstd = rsqrtf(var + 1e-5f);
    }
    __syncthreads();
    float mean = sh_mean, rstd = sh_rstd;
    float4 gv = ((const float4*)g)[tid];
    float4 bv = ((const float4*)b)[tid];
    uint2 hv;
    hv.x = pack2((v.x - mean) * rstd * gv.x + bv.x, (v.y - mean) * rstd * gv.y + bv.y);
    hv.y = pack2((v.z - mean) * rstd * gv.z + bv.z, (v.w - mean) * rstd * gv.w + bv.w);
    *(uint2*)(y + (size_t)row * CC + tid * 4) = hv;
}

// ================= mma.sync GEMM (plain fp16, B K-major) =================
// C = A*B + bias   A[M][K] fp16, B = W[K][gN] fp16 (K-major; trans-ldsm frags)
// E: 1 = fp32 out (+bias+res); 2 = gelu -> fp16; 4 = fp16 (+bias; Q cols x1/8).
#define GS 4
#define SSTRIDE 40                          // A smem row stride (halves)
#define TILE_A (128*SSTRIDE*2)              // 10240 bytes
#define SBST 136                            // B smem row stride (halves) = 272B
#define TILE_BK (32*SBST*2)                 // 8704 bytes
#define STAGE_SZ (TILE_A + TILE_BK)         // 18944
#define GSMEM2 (GS * STAGE_SZ)              // 75776

template<int E>
__global__ void __launch_bounds__(256, 2) gemm_mma(const __half* __restrict__ A,
                                                   const __half* __restrict__ B,
                                                   const float* __restrict__ bias,
                                                   const float* __restrict__ res,
                                                   float* __restrict__ outf,
                                                   __half* __restrict__ outh,
                                                   int K, int gN)
{
    extern __shared__ char smem[];
    uint32_t sbase = smem_to_u32(smem);
    int tid = threadIdx.x, lane = tid & 31, wid = tid >> 5;
    int bx = blockIdx.x, by = blockIdx.y;
    const int NK = K >> 5;
    int m0 = (wid & 3) * 32, n0 = (wid >> 2) * 64;

    const __half* Ap = A + (size_t)(by * 128) * K;
    const __half* Bp = B + bx * 128;         // [K][gN], col offset

    int uA = tid & 3;        // A: 16B unit within 64B row
    int rA = tid >> 2;       // 0..63
    int uB = tid & 15;       // B: 16B unit within 256B row
    int rB = tid >> 4;       // 0..15

    auto issue = [&](int kk) {
        uint32_t st = sbase + (kk & (GS - 1)) * STAGE_SZ;
#pragma unroll
        for (int rr = 0; rr < 2; rr++) {
            int r = rA + rr * 64;
            CP_ASYNC16(st + (r * SSTRIDE + uA * 8) * 2,
                       Ap + (size_t)r * K + kk * 32 + uA * 8);
        }
        uint32_t stB = st + TILE_A;
#pragma unroll
        for (int rr = 0; rr < 2; rr++) {
            int r = rB + rr * 16;
            CP_ASYNC16(stB + (r * SBST + uB * 8) * 2,
                       Bp + (size_t)(kk * 32 + r) * gN + uB * 8);
        }
        CP_COMMIT();
    };

    float acc[2][8][4] = {};

    for (int c = 0; c < GS - 1; c++) issue(c);

    for (int c = 0; c < NK; c++) {
        CP_WAIT(GS - 2);          // stage c complete
        __syncthreads();          // all warps done reading stage (c-1)
        if (c + GS - 1 < NK) issue(c + GS - 1); else CP_COMMIT();

        uint32_t st = sbase + (c & (GS - 1)) * STAGE_SZ;
        uint32_t stB = st + TILE_A;
#pragma unroll
        for (int kh = 0; kh < 2; kh++) {
            uint32_t ah[2][4];
#pragma unroll
            for (int i = 0; i < 2; i++) {
                uint32_t aoff = ((m0 + i * 16 + (lane & 15)) * SSTRIDE + kh * 16 + (lane >> 4) * 8) * 2;
                ldsm4(ah[i], st + aoff);
            }
            // B frags: trans-ldsm over [k][n] tile
            uint32_t boff = (kh * 16 + (lane & 15)) * SBST + n0 + ((lane >> 4) & 1) * 8;
            uint32_t bh[4][4];
#pragma unroll
            for (int g = 0; g < 4; g++) ldsm4t(bh[g], stB + (boff + g * 16) * 2);
#pragma unroll
            for (int i = 0; i < 2; i++)
#pragma unroll
                for (int g = 0; g < 4; g++) {
                    mma16816(acc[i][g * 2 + 0], ah[i], &bh[g][0]);
                    mma16816(acc[i][g * 2 + 1], ah[i], &bh[g][2]);
                }
        }
    }

    // epilogue from registers
    int mb = by * 128 + m0;
    int nb = bx * 128 + n0;
#pragma unroll
    for (int i = 0; i < 2; i++) {
#pragma unroll
        for (int j = 0; j < 8; j++) {
            float* cc = acc[i][j];
            int n = nb + j * 8 + (lane & 3) * 2;
            float b0 = bias[n], b1 = bias[n + 1];
#pragma unroll
            for (int hrow = 0; hrow < 2; hrow++) {
                int m = mb + i * 16 + (lane >> 2) + hrow * 8;
                float v0 = cc[hrow * 2 + 0] + b0;
                float v1 = cc[hrow * 2 + 1] + b1;
                size_t off = (size_t)m * gN + n;
                if (E == 1) {
                    float2 rv = *(const float2*)(res + off);
                    v0 += rv.x; v1 += rv.y;
                    float2 ov; ov.x = v0; ov.y = v1;
                    *(float2*)(outf + off) = ov;
                } else if (E == 4) {
                    // Q columns pre-scaled by 1/sqrt(D)=0.125 (exact pow2)
                    if (n < CC) { v0 *= 0.125f; v1 *= 0.125f; }
                    *(uint32_t*)(outh + off) = pack2(v0, v1);
                } else {
                    v0 = 0.5f * v0 * (1.0f + erff(v0 * 0.70710678118654752f));
                    v1 = 0.5f * v1 * (1.0f + erff(v1 * 0.70710678118654752f));
                    *(uint32_t*)(outh + off) = pack2(v0, v1);
                }
            }
        }
    }
}

// ================= FA2 tensor-core attention (fp16, cp.async) =====
// Q pre-scaled by 1/8 in qkv epilogue. Called per-batch (pointers pre-offset).
#define AST 72        // smem row stride in halves
#define ATILE (64 * AST)                 // halves per tile
#define KVSTAGE (2 * ATILE)              // K,V
#define ASMEM ((ATILE + 2 * KVSTAGE) * 2)   // 46080 bytes

__global__ void __launch_bounds__(128) attn_fa2(const __half* __restrict__ q_g,
                                                __half* __restrict__ o_g)
{
    extern __shared__ __half sb[];
    __half* sQ = sb;
    __half* sKV = sQ + ATILE;    // 2 stages of [K|V]
    uint32_t uQ = smem_to_u32(sQ);
    uint32_t uKV = smem_to_u32(sKV);

    int tid = threadIdx.x, lane = tid & 31, w = tid >> 5;
    int qt = gridDim.x - 1 - blockIdx.x;       // heavy tiles first
    int h = blockIdx.y;
    size_t qbase = ((size_t)(qt * 64)) * QKVC + h * DD;

    int r0 = tid >> 3, uu = tid & 7;

    auto issue_kv = [&](int kt, int s) {
        size_t kbase = ((size_t)(kt * 64)) * QKVC + CC + h * DD;
        size_t vbase = kbase + CC;
        uint32_t st = uKV + s * KVSTAGE * 2;
#pragma unroll
        for (int rep = 0; rep < 4; rep++) {
            int r = r0 + rep * 16;
            size_t go = (size_t)r * QKVC + uu * 8;
            uint32_t so = (r * AST + uu * 8) * 2;
            CP_ASYNC16(st + so,             q_g + kbase + go);
            CP_ASYNC16(st + ATILE * 2 + so, q_g + vbase + go);
        }
        CP_COMMIT();
    };

    issue_kv(0, 0);
#pragma unroll
    for (int rep = 0; rep < 4; rep++) {
        int r = r0 + rep * 16;
        *(uint4*)(sQ + r * AST + uu * 8) = *(const uint4*)(q_g + qbase + (size_t)r * QKVC + uu * 8);
    }
    __syncthreads();

    uint32_t qh[4][4];
#pragma unroll
    for (int ks = 0; ks < 4; ks++) {
        uint32_t off = ((16 * w + (lane & 15)) * AST + ks * 16 + (lane >> 4) * 8) * 2;
        ldsm4(qh[ks], uQ + off);
    }

    float m0r = -1e30f, m1r = -1e30f;
    float l0r = 0.f, l1r = 0.f;
    float oacc[8][4] = {};

    for (int kt = 0; kt <= qt; kt++) {
        int s = kt & 1;
        __syncthreads();
        if (kt + 1 <= qt) issue_kv(kt + 1, s ^ 1); else CP_COMMIT();
        CP_WAIT(1);
        __syncthreads();

        uint32_t uK = uKV + (s * KVSTAGE) * 2;
        uint32_t uV = uK + ATILE * 2;

        // ---- S = QK^T (Q pre-scaled) ----
        float sacc[8][4] = {};
#pragma unroll
        for (int ks = 0; ks < 4; ks++) {
            uint32_t kb[4][4];
            uint32_t boff = ((lane & 7) + ((lane >> 4) & 1) * 8) * AST + ks * 16 + ((lane >> 3) & 1) * 8;
#pragma unroll
            for (int g = 0; g < 4; g++) ldsm4(kb[g], uK + (boff + g * 16 * AST) * 2);
#pragma unroll
            for (int g = 0; g < 4; g++) {
                mma16816(sacc[g * 2 + 0], qh[ks], &kb[g][0]);
                mma16816(sacc[g * 2 + 1], qh[ks], &kb[g][2]);
            }
        }

        // ---- mask, online softmax ----
        int rl0 = w * 16 + (lane >> 2);
        int rl1 = rl0 + 8;
        float mn0 = m0r, mn1 = m1r;
#pragma unroll
        for (int t = 0; t < 8; t++) {
            if (kt == qt) {
                int col = t * 8 + 2 * (lane & 3);
                if (col     > rl0) sacc[t][0] = -1e30f;
                if (col + 1 > rl0) sacc[t][1] = -1e30f;
                if (col     > rl1) sacc[t][2] = -1e30f;
                if (col + 1 > rl1) sacc[t][3] = -1e30f;
            }
            mn0 = fmaxf(mn0, fmaxf(sacc[t][0], sacc[t][1]));
            mn1 = fmaxf(mn1, fmaxf(sacc[t][2], sacc[t][3]));
        }
        mn0 = fmaxf(mn0, __shfl_xor_sync(0xffffffffu, mn0, 1));
        mn0 = fmaxf(mn0, __shfl_xor_sync(0xffffffffu, mn0, 2));
        mn1 = fmaxf(mn1, __shfl_xor_sync(0xffffffffu, mn1, 1));
        mn1 = fmaxf(mn1, __shfl_xor_sync(0xffffffffu, mn1, 2));
        float es0 = __expf(m0r - mn0), es1 = __expf(m1r - mn1);
        m0r = mn0; m1r = mn1;
        float rs0 = 0.f, rs1 = 0.f;
#pragma unroll
        for (int t = 0; t < 8; t++) {
            sacc[t][0] = __expf(sacc[t][0] - mn0);
            sacc[t][1] = __expf(sacc[t][1] - mn0);
            sacc[t][2] = __expf(sacc[t][2] - mn1);
            sacc[t][3] = __expf(sacc[t][3] - mn1);
            rs0 += sacc[t][0] + sacc[t][1];
            rs1 += sacc[t][2] + sacc[t][3];
        }
        rs0 += __shfl_xor_sync(0xffffffffu, rs0, 1);
        rs0 += __shfl_xor_sync(0xffffffffu, rs0, 2);
        rs1 += __shfl_xor_sync(0xffffffffu, rs1, 1);
        rs1 += __shfl_xor_sync(0xffffffffu, rs1, 2);
        l0r = l0r * es0 + rs0;
        l1r = l1r * es1 + rs1;
#pragma unroll
        for (int t = 0; t < 8; t++) {
            oacc[t][0] *= es0; oacc[t][1] *= es0;
            oacc[t][2] *= es1; oacc[t][3] *= es1;
        }

        // ---- PV ----
#pragma unroll
        for (int ks = 0; ks < 4; ks++) {
            uint32_t pa[4];
            pa[0] = pack2(sacc[2 * ks][0],     sacc[2 * ks][1]);
            pa[1] = pack2(sacc[2 * ks][2],     sacc[2 * ks][3]);
            pa[2] = pack2(sacc[2 * ks + 1][0], sacc[2 * ks + 1][1]);
            pa[3] = pack2(sacc[2 * ks + 1][2], sacc[2 * ks + 1][3]);

            uint32_t vb[4][4];
            uint32_t voff = (ks * 16 + (lane & 15)) * AST + ((lane >> 4) & 1) * 8;
#pragma unroll
            for (int g = 0; g < 4; g++) ldsm4t(vb[g], uV + (voff + g * 16) * 2);
#pragma unroll
            for (int g = 0; g < 4; g++) {
                mma16816(oacc[g * 2 + 0], pa, &vb[g][0]);
                mma16816(oacc[g * 2 + 1], pa, &vb[g][2]);
            }
        }
    }

    float inv0 = 1.0f / l0r, inv1 = 1.0f / l1r;
    size_t r0g = (size_t)(qt * 64 + w * 16 + (lane >> 2));
    size_t obase0 = r0g * CC + h * DD;
    size_t obase1 = (r0g + 8) * CC + h * DD;
#pragma unroll
    for (int t = 0; t < 8; t++) {
        int d = t * 8 + 2 * (lane & 3);
        *(uint32_t*)(o_g + obase0 + d) = pack2(oacc[t][0] * inv0, oacc[t][1] * inv0);
        *(uint32_t*)(o_g + obase1 + d) = pack2(oacc[t][2] * inv1, oacc[t][3] * inv1);
    }
}

// ---------------- launch: two independent per-batch chains (lockstep) -------
extern "C" void kernel_launch(void* const* d_in, const int* in_sizes, int n_in,
                              void* d_out, int out_size)
{
    const float* x     = (const float*)d_in[0];
    const float* ln1_g = (const float*)d_in[1];
    const float* ln1_b = (const float*)d_in[2];
    const float* qkv_w = (const float*)d_in[3];
    const float* qkv_b = (const float*)d_in[4];
    const float* out_w = (const float*)d_in[5];
    const float* out_b = (const float*)d_in[6];
    const float* ln2_g = (const float*)d_in[7];
    const float* ln2_b = (const float*)d_in[8];
    const float* ff1_w = (const float*)d_in[9];
    const float* ff1_b = (const float*)d_in[10];
    const float* ff2_w = (const float*)d_in[11];
    const float* ff2_b = (const float*)d_in[12];
    float* y = (float*)d_out;

    float *p_x1;
    __half *p_h, *p_q, *p_a, *p_f;
    __half *p_wq, *p_wo, *p_w1, *p_w2;
    cudaGetSymbolAddress((void**)&p_x1, g_x1);
    cudaGetSymbolAddress((void**)&p_h,  g_h);
    cudaGetSymbolAddress((void**)&p_q,  g_q);
    cudaGetSymbolAddress((void**)&p_a,  g_a);
    cudaGetSymbolAddress((void**)&p_f,  g_f);
    cudaGetSymbolAddress((void**)&p_wq, g_wqkv);
    cudaGetSymbolAddress((void**)&p_wo, g_wout);
    cudaGetSymbolAddress((void**)&p_w1, g_wff1);
    cudaGetSymbolAddress((void**)&p_w2, g_wff2);

    cudaFuncSetAttribute(attn_fa2, cudaFuncAttributeMaxDynamicSharedMemorySize, ASMEM);
    cudaFuncSetAttribute((const void*)gemm_mma<1>, cudaFuncAttributeMaxDynamicSharedMemorySize, GSMEM2);
    cudaFuncSetAttribute((const void*)gemm_mma<2>, cudaFuncAttributeMaxDynamicSharedMemorySize, GSMEM2);
    cudaFuncSetAttribute((const void*)gemm_mma<4>, cudaFuncAttributeMaxDynamicSharedMemorySize, GSMEM2);

    // streams + events, created once OUTSIDE graph capture
    static cudaStream_t s1 = nullptr, s2 = nullptr;
    static cudaEvent_t e0 = nullptr, e_wq = nullptr, e_wmid = nullptr, eB = nullptr;
    if (!s1) {
        cudaStreamCreateWithFlags(&s1, cudaStreamNonBlocking);
        cudaStreamCreateWithFlags(&s2, cudaStreamNonBlocking);
        cudaEventCreateWithFlags(&e0,    cudaEventDisableTiming);
        cudaEventCreateWithFlags(&e_wq,  cudaEventDisableTiming);
        cudaEventCreateWithFlags(&e_wmid,cudaEventDisableTiming);
        cudaEventCreateWithFlags(&eB,    cudaEventDisableTiming);
    }

    // ---- weight converts on s2 ----
    cudaEventRecord(e0, 0);
    cudaStreamWaitEvent(s2, e0, 0);
    wconv_kernel<<<CC * QKVC / 2048, 256, 0, s2>>>(qkv_w, p_wq);
    cudaEventRecord(e_wq, s2);
    wconv_kernel<<<CC * CC / 2048, 256, 0, s2>>>(out_w, p_wo);
    wconv_kernel<<<CC * FF / 2048, 256, 0, s2>>>(ff1_w, p_w1);
    wconv_kernel<<<FF * CC / 2048, 256, 0, s2>>>(ff2_w, p_w2);
    cudaEventRecord(e_wmid, s2);

    // per-batch half sizes (rows = TT)
    const size_t oC  = (size_t)TT * CC;     // half offset, C-wide arrays
    const size_t oQ  = (size_t)TT * QKVC;
    const size_t oF  = (size_t)TT * FF;
    dim3 gQKV(QKVC / 128, TT / 128);
    dim3 gOUT(CC / 128,  TT / 128);
    dim3 gFF1(FF / 128,  TT / 128);
    dim3 gFF2(CC / 128,  TT / 128);
    dim3 gATT(TT / 64, HH, 1);

    // ======== chain A (batch 0) on main stream ========
    ln_kernel<<<TT, 256>>>(x, ln1_g, ln1_b, p_h);
    cudaStreamWaitEvent(0, e_wq, 0);
    gemm_mma<4><<<gQKV, 256, GSMEM2>>>(p_h, p_wq, qkv_b, nullptr, nullptr, p_q, CC, QKVC);
    attn_fa2<<<gATT, 128, ASMEM>>>(p_q, p_a);
    cudaStreamWaitEvent(0, e_wmid, 0);
    gemm_mma<1><<<gOUT, 256, GSMEM2>>>(p_a, p_wo, out_b, x, p_x1, nullptr, CC, CC);
    ln_kernel<<<TT, 256>>>(p_x1, ln2_g, ln2_b, p_h);
    gemm_mma<2><<<gFF1, 256, GSMEM2>>>(p_h, p_w1, ff1_b, nullptr, nullptr, p_f, CC, FF);
    gemm_mma<1><<<gFF2, 256, GSMEM2>>>(p_f, p_w2, ff2_b, p_x1, y, nullptr, FF, CC);

    // ======== chain B (batch 1) on s1 ========
    cudaStreamWaitEvent(s1, e0, 0);
    ln_kernel<<<TT, 256, 0, s1>>>(x + oC, ln1_g, ln1_b, p_h + oC);
    cudaStreamWaitEvent(s1, e_wq, 0);
    gemm_mma<4><<<gQKV, 256, GSMEM2, s1>>>(p_h + oC, p_wq, qkv_b, nullptr, nullptr, p_q + oQ, CC, QKVC);
    attn_fa2<<<gATT, 128, ASMEM, s1>>>(p_q + oQ, p_a + oC);
    cudaStreamWaitEvent(s1, e_wmid, 0);
    gemm_mma<1><<<gOUT, 256, GSMEM2, s1>>>(p_a + oC, p_wo, out_b, x + oC, p_x1 + oC, nullptr, CC, CC);
    ln_kernel<<<TT, 256, 0, s1>>>(p_x1 + oC, ln2_g, ln2_b, p_h + oC);
    gemm_mma<2><<<gFF1, 256, GSMEM2, s1>>>(p_h + oC, p_w1, ff1_b, nullptr, nullptr, p_f + oF, CC, FF);
    gemm_mma<1><<<gFF2, 256, GSMEM2, s1>>>(p_f + oF, p_w2, ff2_b, p_x1 + oC, y + oC, nullptr, FF, CC);
    cudaEventRecord(eB, s1);

    // join
    cudaStreamWaitEvent(0, eB, 0);
}